// round 1
// baseline (speedup 1.0000x reference)
#include <cuda_runtime.h>
#include <math.h>

#define NN 131072
#define EE 1000000

// ---------------- static device scratch (no allocs allowed) ----------------
__device__ float gXA[NN * 64];
__device__ float gXB[NN * 64];
__device__ float gBufA[(size_t)NN * 320];   // [q | kr0 | vr0 | kr2 | vr2]
__device__ float gBufB[(size_t)NN * 192];   // [q | kr1 | vr1]
__device__ float gAggA[NN * 64];
__device__ float gAggB[NN * 64];
__device__ float gWfA[64 * 320];
__device__ float gBfA[320];
__device__ float gWfB[64 * 192];
__device__ float gBfB[192];
__device__ int   gRowptr[3][NN + 1];
__device__ int   gCur[NN];
__device__ int   gCsr[3][EE];

// ---------------- helpers ----------------
__device__ __forceinline__ float warpsum(float p) {
    p += __shfl_xor_sync(0xffffffffu, p, 16);
    p += __shfl_xor_sync(0xffffffffu, p, 8);
    p += __shfl_xor_sync(0xffffffffu, p, 4);
    p += __shfl_xor_sync(0xffffffffu, p, 2);
    p += __shfl_xor_sync(0xffffffffu, p, 1);
    return p;
}

__device__ __forceinline__ float gelu_f(float v) {
    return 0.5f * v * (1.0f + erff(v * 0.7071067811865476f));
}

// ---------------- input staging ----------------
__global__ void k_copyin(const float* __restrict__ xA, const float* __restrict__ xB) {
    int i = blockIdx.x * blockDim.x + threadIdx.x;   // grid covers NN*64 exactly
    gXA[i] = xA[i];
    gXB[i] = xB[i];
}

// ---------------- CSR build (edges fixed across layers) ----------------
__global__ void k_zero_deg(int rel) {
    int i = blockIdx.x * blockDim.x + threadIdx.x;
    if (i < NN) gRowptr[rel][i] = 0;
}

__global__ void k_hist(const int* __restrict__ ei, int rel) {
    int e = blockIdx.x * blockDim.x + threadIdx.x;
    if (e < EE) atomicAdd(&gRowptr[rel][ei[EE + e]], 1);
}

// single-block deterministic exclusive scan over NN degrees (in place)
__global__ void k_scan(int rel) {
    __shared__ int wsum[32];
    __shared__ int carrySh;
    int tid = threadIdx.x, lane = tid & 31, wid = tid >> 5;
    if (tid == 0) carrySh = 0;
    __syncthreads();
    for (int base = 0; base < NN; base += 1024) {
        int v = gRowptr[rel][base + tid];
        int x = v;
#pragma unroll
        for (int o = 1; o < 32; o <<= 1) {
            int y = __shfl_up_sync(0xffffffffu, x, o);
            if (lane >= o) x += y;
        }
        if (lane == 31) wsum[wid] = x;
        __syncthreads();
        if (wid == 0) {
            int s = wsum[lane];
#pragma unroll
            for (int o = 1; o < 32; o <<= 1) {
                int y = __shfl_up_sync(0xffffffffu, s, o);
                if (lane >= o) s += y;
            }
            wsum[lane] = s;
        }
        __syncthreads();
        int carry = carrySh;
        int incl = x + (wid ? wsum[wid - 1] : 0) + carry;
        gRowptr[rel][base + tid] = incl - v;   // exclusive
        gCur[base + tid] = incl - v;           // scatter cursor
        __syncthreads();
        if (tid == 1023) carrySh = incl;
        __syncthreads();
    }
    if (threadIdx.x == 0) gRowptr[rel][NN] = carrySh;
}

__global__ void k_scatter(const int* __restrict__ ei, int rel) {
    int e = blockIdx.x * blockDim.x + threadIdx.x;
    if (e >= EE) return;
    int dst = ei[EE + e];
    int src = ei[e];
    int pos = atomicAdd(&gCur[dst], 1);
    gCsr[rel][pos] = src;
}

// ---------------- per-layer fused weight build ----------------
// WfA[64x320] = [Wq_A | Wk_A@a0 | Wv_A@m0 | Wk_A@a2 | Wv_A@m2], WfB[64x192] analog (rel 1)
__global__ void k_fuse(const float* __restrict__ Wk, const float* __restrict__ bk,
                       const float* __restrict__ Wq, const float* __restrict__ bq,
                       const float* __restrict__ Wv, const float* __restrict__ bv,
                       const float* __restrict__ Ar, const float* __restrict__ Mr, int l) {
    int id = blockIdx.x * blockDim.x + threadIdx.x;
    const int WA = 64 * 320, WB = 64 * 192;
    if (id < WA) {
        int i = id / 320, j = id % 320;
        int g = j >> 6, jj = j & 63;
        float val;
        if (g == 0) val = Wq[(size_t)(l * 2 + 0) * 4096 + i * 64 + jj];
        else {
            const float* Wsrc = (g == 1 || g == 3) ? Wk : Wv;
            const float* R    = (g == 1 || g == 3) ? Ar : Mr;
            int r = (g <= 2) ? 0 : 2;
            const float* w = Wsrc + (size_t)(l * 2 + 0) * 4096 + i * 64;
            const float* a = R + (size_t)(l * 3 + r) * 4096;
            float s = 0.f;
#pragma unroll
            for (int d = 0; d < 64; d++) s += w[d] * a[d * 64 + jj];
            val = s;
        }
        gWfA[id] = val;
    } else if (id < WA + WB) {
        int idx = id - WA;
        int i = idx / 192, j = idx % 192;
        int g = j >> 6, jj = j & 63;
        float val;
        if (g == 0) val = Wq[(size_t)(l * 2 + 1) * 4096 + i * 64 + jj];
        else {
            const float* Wsrc = (g == 1) ? Wk : Wv;
            const float* R    = (g == 1) ? Ar : Mr;
            const float* w = Wsrc + (size_t)(l * 2 + 1) * 4096 + i * 64;
            const float* a = R + (size_t)(l * 3 + 1) * 4096;
            float s = 0.f;
#pragma unroll
            for (int d = 0; d < 64; d++) s += w[d] * a[d * 64 + jj];
            val = s;
        }
        gWfB[idx] = val;
    } else if (id < WA + WB + 320) {
        int j = id - (WA + WB);
        int g = j >> 6, jj = j & 63;
        float val;
        if (g == 0) val = bq[(l * 2 + 0) * 64 + jj];
        else {
            const float* bsrc = (g == 1 || g == 3) ? bk : bv;
            const float* R    = (g == 1 || g == 3) ? Ar : Mr;
            int r = (g <= 2) ? 0 : 2;
            const float* b = bsrc + (l * 2 + 0) * 64;
            const float* a = R + (size_t)(l * 3 + r) * 4096;
            float s = 0.f;
            for (int d = 0; d < 64; d++) s += b[d] * a[d * 64 + jj];
            val = s;
        }
        gBfA[j] = val;
    } else if (id < WA + WB + 320 + 192) {
        int j = id - (WA + WB + 320);
        int g = j >> 6, jj = j & 63;
        float val;
        if (g == 0) val = bq[(l * 2 + 1) * 64 + jj];
        else {
            const float* bsrc = (g == 1) ? bk : bv;
            const float* R    = (g == 1) ? Ar : Mr;
            const float* b = bsrc + (l * 2 + 1) * 64;
            const float* a = R + (size_t)(l * 3 + 1) * 4096;
            float s = 0.f;
            for (int d = 0; d < 64; d++) s += b[d] * a[d * 64 + jj];
            val = s;
        }
        gBfB[j] = val;
    }
}

// ---------------- wide projection GEMM: buf = x @ Wf + bf ----------------
__global__ void __launch_bounds__(256) k_proj(int typ) {
    const float* X   = typ ? gXB  : gXA;
    const float* Wf  = typ ? gWfB : gWfA;
    const float* Bf  = typ ? gBfB : gBfA;
    float*       Out = typ ? gBufB : gBufA;
    const int OC = typ ? 192 : 320;
    int cg = blockIdx.y;

    __shared__ __align__(16) float Ws[4096];
    __shared__ float Bs[64];
    for (int i = threadIdx.x; i < 4096; i += 256) {
        int k = i >> 6, j = i & 63;
        Ws[i] = Wf[k * OC + cg * 64 + j];
    }
    if (threadIdx.x < 64) Bs[threadIdx.x] = Bf[cg * 64 + threadIdx.x];
    __syncthreads();

    size_t r = (size_t)blockIdx.x * 256 + threadIdx.x;
    float x[64];
    const float4* xr = (const float4*)(X + r * 64);
#pragma unroll
    for (int i = 0; i < 16; i++) {
        float4 t = xr[i];
        x[4*i] = t.x; x[4*i+1] = t.y; x[4*i+2] = t.z; x[4*i+3] = t.w;
    }
    float4* outp = (float4*)(Out + r * OC + cg * 64);
#pragma unroll
    for (int c = 0; c < 4; c++) {
        float acc[16];
#pragma unroll
        for (int j = 0; j < 16; j++) acc[j] = Bs[c * 16 + j];
#pragma unroll
        for (int k = 0; k < 64; k++) {
            const float4* w4 = (const float4*)(Ws + k * 64 + c * 16);
            float xv = x[k];
            float4 w0 = w4[0], w1 = w4[1], w2 = w4[2], w3 = w4[3];
            acc[0]  += xv * w0.x; acc[1]  += xv * w0.y; acc[2]  += xv * w0.z; acc[3]  += xv * w0.w;
            acc[4]  += xv * w1.x; acc[5]  += xv * w1.y; acc[6]  += xv * w1.z; acc[7]  += xv * w1.w;
            acc[8]  += xv * w2.x; acc[9]  += xv * w2.y; acc[10] += xv * w2.z; acc[11] += xv * w2.w;
            acc[12] += xv * w3.x; acc[13] += xv * w3.y; acc[14] += xv * w3.z; acc[15] += xv * w3.w;
        }
#pragma unroll
        for (int q = 0; q < 4; q++)
            outp[c * 4 + q] = make_float4(acc[q*4], acc[q*4+1], acc[q*4+2], acc[q*4+3]);
    }
}

// ---------------- edge attention: warp per dst node, two-pass softmax ----------------
__device__ __forceinline__ void rel_accum(int gw, int lane, float q0, float q1,
                                          const float* __restrict__ srcBuf, int stride,
                                          int krOff, int vrOff,
                                          const int* __restrict__ rowptr,
                                          const int* __restrict__ csr,
                                          float scl, float& a0, float& a1) {
    int beg = rowptr[gw], end = rowptr[gw + 1];
    float mx = -3.0e38f;
    for (int j = beg; j < end; j++) {
        int s = csr[j];
        float2 kv = *(const float2*)(srcBuf + (size_t)s * stride + krOff + 2 * lane);
        float sc = warpsum(q0 * kv.x + q1 * kv.y) * scl;
        mx = fmaxf(mx, sc);
    }
    float den = 0.f, s0 = 0.f, s1 = 0.f;
    for (int j = beg; j < end; j++) {
        int s = csr[j];
        float2 kv = *(const float2*)(srcBuf + (size_t)s * stride + krOff + 2 * lane);
        float sc = warpsum(q0 * kv.x + q1 * kv.y) * scl;
        float ex = __expf(sc - mx);
        float2 vv = *(const float2*)(srcBuf + (size_t)s * stride + vrOff + 2 * lane);
        den += ex;
        s0 += ex * vv.x;
        s1 += ex * vv.y;
    }
    if (den > 0.f) {
        float inv = 1.0f / den;
        a0 += s0 * inv;
        a1 += s1 * inv;
    }
}

__global__ void k_edge_A(const float* __restrict__ p_rel, int l) {
    int t = blockIdx.x * blockDim.x + threadIdx.x;
    int gw = t >> 5, lane = t & 31;
    if (gw >= NN) return;
    float q0 = gBufA[(size_t)gw * 320 + 2 * lane];
    float q1 = gBufA[(size_t)gw * 320 + 2 * lane + 1];
    float a0 = 0.f, a1 = 0.f;
    // relation 1: B -> A
    rel_accum(gw, lane, q0, q1, gBufB, 192, 64, 128, gRowptr[1], gCsr[1],
              p_rel[l * 3 + 1] * 0.125f, a0, a1);
    // relation 2: A -> A
    rel_accum(gw, lane, q0, q1, gBufA, 320, 192, 256, gRowptr[2], gCsr[2],
              p_rel[l * 3 + 2] * 0.125f, a0, a1);
    gAggA[(size_t)gw * 64 + 2 * lane]     = a0;
    gAggA[(size_t)gw * 64 + 2 * lane + 1] = a1;
}

__global__ void k_edge_B(const float* __restrict__ p_rel, int l) {
    int t = blockIdx.x * blockDim.x + threadIdx.x;
    int gw = t >> 5, lane = t & 31;
    if (gw >= NN) return;
    float q0 = gBufB[(size_t)gw * 192 + 2 * lane];
    float q1 = gBufB[(size_t)gw * 192 + 2 * lane + 1];
    float a0 = 0.f, a1 = 0.f;
    // relation 0: A -> B
    rel_accum(gw, lane, q0, q1, gBufA, 320, 64, 128, gRowptr[0], gCsr[0],
              p_rel[l * 3 + 0] * 0.125f, a0, a1);
    gAggB[(size_t)gw * 64 + 2 * lane]     = a0;
    gAggB[(size_t)gw * 64 + 2 * lane + 1] = a1;
}

// ---------------- output projection + skip, in-place x update ----------------
__global__ void __launch_bounds__(256) k_out(int typ, const float* __restrict__ Wa,
                                             const float* __restrict__ ba,
                                             const float* __restrict__ skip, int l) {
    __shared__ __align__(16) float Ws[4096];
    __shared__ float Bs[64];
    const float* agg = typ ? gAggB : gAggA;
    float* X = typ ? gXB : gXA;
    const float* w = Wa + (size_t)(l * 2 + typ) * 4096;
    for (int i = threadIdx.x; i < 4096; i += 256) Ws[i] = w[i];
    if (threadIdx.x < 64) Bs[threadIdx.x] = ba[(l * 2 + typ) * 64 + threadIdx.x];
    __syncthreads();

    float sg = 1.0f / (1.0f + __expf(-skip[l * 2 + typ]));
    float omg = 1.0f - sg;
    size_t r = (size_t)blockIdx.x * 256 + threadIdx.x;

    float g[64];
    const float4* ar = (const float4*)(agg + r * 64);
#pragma unroll
    for (int i = 0; i < 16; i++) {
        float4 t = ar[i];
        g[4*i]   = gelu_f(t.x);
        g[4*i+1] = gelu_f(t.y);
        g[4*i+2] = gelu_f(t.z);
        g[4*i+3] = gelu_f(t.w);
    }
    float4* xr = (float4*)(X + r * 64);
#pragma unroll
    for (int c = 0; c < 4; c++) {
        float acc[16];
#pragma unroll
        for (int j = 0; j < 16; j++) acc[j] = Bs[c * 16 + j];
#pragma unroll
        for (int k = 0; k < 64; k++) {
            const float4* w4 = (const float4*)(Ws + k * 64 + c * 16);
            float xv = g[k];
            float4 w0 = w4[0], w1 = w4[1], w2 = w4[2], w3 = w4[3];
            acc[0]  += xv * w0.x; acc[1]  += xv * w0.y; acc[2]  += xv * w0.z; acc[3]  += xv * w0.w;
            acc[4]  += xv * w1.x; acc[5]  += xv * w1.y; acc[6]  += xv * w1.z; acc[7]  += xv * w1.w;
            acc[8]  += xv * w2.x; acc[9]  += xv * w2.y; acc[10] += xv * w2.z; acc[11] += xv * w2.w;
            acc[12] += xv * w3.x; acc[13] += xv * w3.y; acc[14] += xv * w3.z; acc[15] += xv * w3.w;
        }
#pragma unroll
        for (int q = 0; q < 4; q++) {
            float4 xo = xr[c * 4 + q];
            float4 o;
            o.x = sg * acc[q*4+0] + omg * xo.x;
            o.y = sg * acc[q*4+1] + omg * xo.y;
            o.z = sg * acc[q*4+2] + omg * xo.z;
            o.w = sg * acc[q*4+3] + omg * xo.w;
            xr[c * 4 + q] = o;
        }
    }
}

// ---------------- final pool + linear ----------------
__global__ void k_zero_out(float* out) { out[0] = 0.f; }

__global__ void k_final(const float* __restrict__ lw, const float* __restrict__ lb,
                        float* out) {
    float acc = 0.f;
    const int total = 2 * NN * 64;
    for (int i = blockIdx.x * blockDim.x + threadIdx.x; i < total;
         i += gridDim.x * blockDim.x) {
        float v = (i < NN * 64) ? gXA[i] : gXB[i - NN * 64];
        acc += v * lw[i & 63];
    }
    __shared__ float red[256];
    red[threadIdx.x] = acc;
    __syncthreads();
    for (int s = 128; s; s >>= 1) {
        if (threadIdx.x < s) red[threadIdx.x] += red[threadIdx.x + s];
        __syncthreads();
    }
    if (threadIdx.x == 0) {
        float v = red[0];
        if (blockIdx.x == 0) v += lb[0];
        atomicAdd(out, v);
    }
}

// ---------------- launch ----------------
extern "C" void kernel_launch(void* const* d_in, const int* in_sizes, int n_in,
                              void* d_out, int out_size) {
    const float* xA   = (const float*)d_in[0];
    const float* xB   = (const float*)d_in[1];
    const float* Wk   = (const float*)d_in[2];
    const float* bk   = (const float*)d_in[3];
    const float* Wq   = (const float*)d_in[4];
    const float* bq   = (const float*)d_in[5];
    const float* Wv   = (const float*)d_in[6];
    const float* bv   = (const float*)d_in[7];
    const float* Ar   = (const float*)d_in[8];
    const float* Mr   = (const float*)d_in[9];
    const float* pr   = (const float*)d_in[10];
    const float* Wa   = (const float*)d_in[11];
    const float* ba   = (const float*)d_in[12];
    const float* skip = (const float*)d_in[13];
    const float* lw   = (const float*)d_in[14];
    const float* lb   = (const float*)d_in[15];
    const int* ei[3]  = {(const int*)d_in[16], (const int*)d_in[17], (const int*)d_in[18]};

    k_copyin<<<NN * 64 / 256, 256>>>(xA, xB);

    for (int r = 0; r < 3; r++) {
        k_zero_deg<<<NN / 256, 256>>>(r);
        k_hist<<<(EE + 255) / 256, 256>>>(ei[r], r);
        k_scan<<<1, 1024>>>(r);
        k_scatter<<<(EE + 255) / 256, 256>>>(ei[r], r);
    }

    for (int l = 0; l < 3; l++) {
        k_fuse<<<131, 256>>>(Wk, bk, Wq, bq, Wv, bv, Ar, Mr, l);
        k_proj<<<dim3(512, 5), 256>>>(0);
        k_proj<<<dim3(512, 3), 256>>>(1);
        k_edge_B<<<16384, 256>>>(pr, l);
        k_edge_A<<<16384, 256>>>(pr, l);
        k_out<<<512, 256>>>(0, Wa, ba, skip, l);
        k_out<<<512, 256>>>(1, Wa, ba, skip, l);
    }

    k_zero_out<<<1, 1>>>((float*)d_out);
    k_final<<<1024, 256>>>(lw, lb, (float*)d_out);
}

// round 2
// speedup vs baseline: 1.3109x; 1.3109x over previous
#include <cuda_runtime.h>
#include <math.h>

#define NN 131072
#define EE 1000000

// ---------------- static device scratch (no allocs allowed) ----------------
__device__ __align__(128) float gXA[NN * 64];
__device__ __align__(128) float gXB[NN * 64];
__device__ __align__(128) float gBufA[(size_t)NN * 320]; // [q | rel0 kv-interleaved | rel2 kv-interleaved]
__device__ __align__(128) float gBufB[(size_t)NN * 192]; // [q | rel1 kv-interleaved]
__device__ __align__(128) float gAggA[NN * 64];
__device__ __align__(128) float gAggB[NN * 64];
__device__ __align__(128) float gWfA[64 * 320];
__device__ float gBfA[320];
__device__ __align__(128) float gWfB[64 * 192];
__device__ float gBfB[192];
__device__ int   gRowptr[3][NN + 1];
__device__ int   gCur3[3][NN];
__device__ int   gBlkSum[3][128];
__device__ int   gCsr[3][EE];

// ---------------- helpers ----------------
__device__ __forceinline__ float warpsum(float p) {
    p += __shfl_xor_sync(0xffffffffu, p, 16);
    p += __shfl_xor_sync(0xffffffffu, p, 8);
    p += __shfl_xor_sync(0xffffffffu, p, 4);
    p += __shfl_xor_sync(0xffffffffu, p, 2);
    p += __shfl_xor_sync(0xffffffffu, p, 1);
    return p;
}

__device__ __forceinline__ int wscan_incl(int x, int lane) {
#pragma unroll
    for (int o = 1; o < 32; o <<= 1) {
        int y = __shfl_up_sync(0xffffffffu, x, o);
        if (lane >= o) x += y;
    }
    return x;
}

__device__ __forceinline__ float gelu_f(float v) {
    return 0.5f * v * (1.0f + erff(v * 0.7071067811865476f));
}

// ---------------- input staging ----------------
__global__ void k_copyin(const float* __restrict__ xA, const float* __restrict__ xB) {
    int i = blockIdx.x * blockDim.x + threadIdx.x;
    gXA[i] = xA[i];
    gXB[i] = xB[i];
}

// ---------------- CSR build (all relations batched via gridDim.y) -----------
__global__ void k_zero_deg() {
    int rel = blockIdx.y;
    int i = blockIdx.x * blockDim.x + threadIdx.x;
    if (i < NN) gRowptr[rel][i] = 0;
}

__global__ void k_hist(const int* __restrict__ e0, const int* __restrict__ e1,
                       const int* __restrict__ e2) {
    int rel = blockIdx.y;
    const int* ei = rel == 0 ? e0 : rel == 1 ? e1 : e2;
    int e = blockIdx.x * blockDim.x + threadIdx.x;
    if (e < EE) atomicAdd(&gRowptr[rel][ei[EE + e]], 1);
}

// per-block sums of degrees: grid (128, 3), 1024 threads
__global__ void k_blocksum() {
    int rel = blockIdx.y;
    int i = blockIdx.x * 1024 + threadIdx.x;
    int lane = threadIdx.x & 31, wid = threadIdx.x >> 5;
    int s = gRowptr[rel][i];
    s = (int)warpsum((float)0), s = gRowptr[rel][i];  // (avoid fp path; do int reduce below)
#pragma unroll
    for (int o = 16; o; o >>= 1) s += __shfl_xor_sync(0xffffffffu, s, o);
    __shared__ int sh[32];
    if (lane == 0) sh[wid] = s;
    __syncthreads();
    if (wid == 0) {
        int t = sh[lane];
#pragma unroll
        for (int o = 16; o; o >>= 1) t += __shfl_xor_sync(0xffffffffu, t, o);
        if (lane == 0) gBlkSum[rel][blockIdx.x] = t;
    }
}

// exclusive scan of the 128 block sums, all 3 relations: 1 block, 128 threads
__global__ void k_scanblk() {
    int tid = threadIdx.x, lane = tid & 31, wid = tid >> 5;
    __shared__ int ws[4];
    for (int rel = 0; rel < 3; rel++) {
        int v = gBlkSum[rel][tid];
        int x = wscan_incl(v, lane);
        __syncthreads();
        if (lane == 31) ws[wid] = x;
        __syncthreads();
        int add = 0;
#pragma unroll
        for (int w = 0; w < 4; w++) add += (w < wid) ? ws[w] : 0;
        gBlkSum[rel][tid] = x + add - v;  // exclusive
        __syncthreads();
    }
}

// local exclusive scan + block offset: grid (128, 3), 1024 threads
__global__ void k_scanlocal() {
    int rel = blockIdx.y;
    int idx = blockIdx.x * 1024 + threadIdx.x;
    int lane = threadIdx.x & 31, wid = threadIdx.x >> 5;
    int v = gRowptr[rel][idx];
    int x = wscan_incl(v, lane);
    __shared__ int ws[32];
    if (lane == 31) ws[wid] = x;
    __syncthreads();
    if (wid == 0) ws[lane] = wscan_incl(ws[lane], lane);
    __syncthreads();
    int incl = x + (wid ? ws[wid - 1] : 0);
    int excl = incl - v + gBlkSum[rel][blockIdx.x];
    gRowptr[rel][idx] = excl;
    gCur3[rel][idx] = excl;
    if (idx == NN - 1) gRowptr[rel][NN] = excl + v;
}

__global__ void k_scatter(const int* __restrict__ e0, const int* __restrict__ e1,
                          const int* __restrict__ e2) {
    int rel = blockIdx.y;
    const int* ei = rel == 0 ? e0 : rel == 1 ? e1 : e2;
    int e = blockIdx.x * blockDim.x + threadIdx.x;
    if (e >= EE) return;
    int dst = ei[EE + e];
    int pos = atomicAdd(&gCur3[rel][dst], 1);
    gCsr[rel][pos] = ei[e];
}

// ---------------- per-layer fused weight build (with kv interleave perm) ----
// Column layout per type:
//   A (OC=320): [ q(64) | rel0: lane-major (k0,k1,v0,v1)x32 | rel2: same ]
//   B (OC=192): [ q(64) | rel1: lane-major (k0,k1,v0,v1)x32 ]
__device__ float fuse_elem(int typ, int i, int j, int l,
                           const float* __restrict__ Wk, const float* __restrict__ bk,
                           const float* __restrict__ Wq, const float* __restrict__ bq,
                           const float* __restrict__ Wv, const float* __restrict__ bv,
                           const float* __restrict__ Ar, const float* __restrict__ Mr) {
    if (j < 64) {
        if (i >= 0) return Wq[(size_t)(l * 2 + typ) * 4096 + i * 64 + j];
        return bq[(l * 2 + typ) * 64 + j];
    }
    int t = j - 64, rel;
    if (typ == 0) { rel = (t >> 7) ? 2 : 0; t &= 127; }
    else rel = 1;
    int lane = t >> 2, c = t & 3;
    int isK = (c < 2);
    int dcol = 2 * lane + (c & 1);
    const float* R = (isK ? Ar : Mr) + (size_t)(l * 3 + rel) * 4096;
    float s = 0.f;
    if (i >= 0) {
        const float* w = (isK ? Wk : Wv) + (size_t)(l * 2 + typ) * 4096 + i * 64;
#pragma unroll
        for (int d = 0; d < 64; d++) s += w[d] * R[d * 64 + dcol];
    } else {
        const float* b = (isK ? bk : bv) + (l * 2 + typ) * 64;
#pragma unroll
        for (int d = 0; d < 64; d++) s += b[d] * R[d * 64 + dcol];
    }
    return s;
}

__global__ void k_fuse(const float* __restrict__ Wk, const float* __restrict__ bk,
                       const float* __restrict__ Wq, const float* __restrict__ bq,
                       const float* __restrict__ Wv, const float* __restrict__ bv,
                       const float* __restrict__ Ar, const float* __restrict__ Mr, int l) {
    int id = blockIdx.x * blockDim.x + threadIdx.x;
    if (id < 20480) {
        int i = id / 320, j = id % 320;
        gWfA[id] = fuse_elem(0, i, j, l, Wk, bk, Wq, bq, Wv, bv, Ar, Mr);
    } else if (id < 32768) {
        int idx = id - 20480;
        int i = idx / 192, j = idx % 192;
        gWfB[idx] = fuse_elem(1, i, j, l, Wk, bk, Wq, bq, Wv, bv, Ar, Mr);
    } else if (id < 33088) {
        int j = id - 32768;
        gBfA[j] = fuse_elem(0, -1, j, l, Wk, bk, Wq, bq, Wv, bv, Ar, Mr);
    } else if (id < 33280) {
        int j = id - 33088;
        gBfB[j] = fuse_elem(1, -1, j, l, Wk, bk, Wq, bq, Wv, bv, Ar, Mr);
    }
}

// ---------------- wide projection GEMM: buf = x @ Wf + bf ----------------
__global__ void __launch_bounds__(256) k_proj(int typ) {
    const float* X   = typ ? gXB  : gXA;
    const float* Wf  = typ ? gWfB : gWfA;
    const float* Bf  = typ ? gBfB : gBfA;
    float*       Out = typ ? gBufB : gBufA;
    const int OC = typ ? 192 : 320;
    int cg = blockIdx.y;

    __shared__ __align__(16) float Ws[4096];
    __shared__ float Bs[64];
    for (int i = threadIdx.x; i < 4096; i += 256) {
        int k = i >> 6, j = i & 63;
        Ws[i] = Wf[k * OC + cg * 64 + j];
    }
    if (threadIdx.x < 64) Bs[threadIdx.x] = Bf[cg * 64 + threadIdx.x];
    __syncthreads();

    size_t r = (size_t)blockIdx.x * 256 + threadIdx.x;
    float x[64];
    const float4* xr = (const float4*)(X + r * 64);
#pragma unroll
    for (int i = 0; i < 16; i++) {
        float4 t = xr[i];
        x[4*i] = t.x; x[4*i+1] = t.y; x[4*i+2] = t.z; x[4*i+3] = t.w;
    }
    float4* outp = (float4*)(Out + r * OC + cg * 64);
#pragma unroll
    for (int c = 0; c < 4; c++) {
        float acc[16];
#pragma unroll
        for (int j = 0; j < 16; j++) acc[j] = Bs[c * 16 + j];
#pragma unroll
        for (int k = 0; k < 64; k++) {
            const float4* w4 = (const float4*)(Ws + k * 64 + c * 16);
            float xv = x[k];
            float4 w0 = w4[0], w1 = w4[1], w2 = w4[2], w3 = w4[3];
            acc[0]  += xv * w0.x; acc[1]  += xv * w0.y; acc[2]  += xv * w0.z; acc[3]  += xv * w0.w;
            acc[4]  += xv * w1.x; acc[5]  += xv * w1.y; acc[6]  += xv * w1.z; acc[7]  += xv * w1.w;
            acc[8]  += xv * w2.x; acc[9]  += xv * w2.y; acc[10] += xv * w2.z; acc[11] += xv * w2.w;
            acc[12] += xv * w3.x; acc[13] += xv * w3.y; acc[14] += xv * w3.z; acc[15] += xv * w3.w;
        }
#pragma unroll
        for (int q = 0; q < 4; q++)
            outp[c * 4 + q] = make_float4(acc[q*4], acc[q*4+1], acc[q*4+2], acc[q*4+3]);
    }
}

// ---------------- edge attention: warp/dst, ONE-PASS online softmax ---------
__device__ __forceinline__ void rel_accum(int gw, int lane, float q0, float q1,
                                          const float* __restrict__ srcBuf, int stride,
                                          int off,
                                          const int* __restrict__ rowptr,
                                          const int* __restrict__ csr,
                                          float scl, float& a0, float& a1) {
    int beg = rowptr[gw], end = rowptr[gw + 1];
    float mx = -3.0e38f, den = 0.f, s0 = 0.f, s1 = 0.f;
    for (int j = beg; j < end; j++) {
        int s = __ldg(&csr[j]);
        float4 kv = *(const float4*)(srcBuf + (size_t)s * stride + off + 4 * lane);
        float sc = warpsum(fmaf(q0, kv.x, q1 * kv.y)) * scl;
        if (sc > mx) {                      // warp-uniform branch
            float f = __expf(mx - sc);      // first iter: exp(-huge) = 0
            den = den * f + 1.f;
            s0  = s0 * f + kv.z;
            s1  = s1 * f + kv.w;
            mx = sc;
        } else {
            float ex = __expf(sc - mx);
            den += ex;
            s0  += ex * kv.z;
            s1  += ex * kv.w;
        }
    }
    if (den > 0.f) {
        float inv = 1.0f / den;
        a0 += s0 * inv;
        a1 += s1 * inv;
    }
}

__global__ void k_edge_A(const float* __restrict__ p_rel, int l) {
    int t = blockIdx.x * blockDim.x + threadIdx.x;
    int gw = t >> 5, lane = t & 31;
    if (gw >= NN) return;
    float2 q = *(const float2*)(gBufA + (size_t)gw * 320 + 2 * lane);
    float a0 = 0.f, a1 = 0.f;
    // relation 1: B -> A (kv at cols 64..191 of gBufB)
    rel_accum(gw, lane, q.x, q.y, gBufB, 192, 64, gRowptr[1], gCsr[1],
              p_rel[l * 3 + 1] * 0.125f, a0, a1);
    // relation 2: A -> A (kv at cols 192..319 of gBufA)
    rel_accum(gw, lane, q.x, q.y, gBufA, 320, 192, gRowptr[2], gCsr[2],
              p_rel[l * 3 + 2] * 0.125f, a0, a1);
    *(float2*)(gAggA + (size_t)gw * 64 + 2 * lane) = make_float2(a0, a1);
}

__global__ void k_edge_B(const float* __restrict__ p_rel, int l) {
    int t = blockIdx.x * blockDim.x + threadIdx.x;
    int gw = t >> 5, lane = t & 31;
    if (gw >= NN) return;
    float2 q = *(const float2*)(gBufB + (size_t)gw * 192 + 2 * lane);
    float a0 = 0.f, a1 = 0.f;
    // relation 0: A -> B (kv at cols 64..191 of gBufA)
    rel_accum(gw, lane, q.x, q.y, gBufA, 320, 64, gRowptr[0], gCsr[0],
              p_rel[l * 3 + 0] * 0.125f, a0, a1);
    *(float2*)(gAggB + (size_t)gw * 64 + 2 * lane) = make_float2(a0, a1);
}

// ---------------- output projection + skip, in-place x update ----------------
__global__ void __launch_bounds__(256) k_out(int typ, const float* __restrict__ Wa,
                                             const float* __restrict__ ba,
                                             const float* __restrict__ skip, int l) {
    __shared__ __align__(16) float Ws[4096];
    __shared__ float Bs[64];
    const float* agg = typ ? gAggB : gAggA;
    float* X = typ ? gXB : gXA;
    const float* w = Wa + (size_t)(l * 2 + typ) * 4096;
    for (int i = threadIdx.x; i < 4096; i += 256) Ws[i] = w[i];
    if (threadIdx.x < 64) Bs[threadIdx.x] = ba[(l * 2 + typ) * 64 + threadIdx.x];
    __syncthreads();

    float sg = 1.0f / (1.0f + __expf(-skip[l * 2 + typ]));
    float omg = 1.0f - sg;
    size_t r = (size_t)blockIdx.x * 256 + threadIdx.x;

    float g[64];
    const float4* ar = (const float4*)(agg + r * 64);
#pragma unroll
    for (int i = 0; i < 16; i++) {
        float4 t = ar[i];
        g[4*i]   = gelu_f(t.x);
        g[4*i+1] = gelu_f(t.y);
        g[4*i+2] = gelu_f(t.z);
        g[4*i+3] = gelu_f(t.w);
    }
    float4* xr = (float4*)(X + r * 64);
#pragma unroll
    for (int c = 0; c < 4; c++) {
        float acc[16];
#pragma unroll
        for (int j = 0; j < 16; j++) acc[j] = Bs[c * 16 + j];
#pragma unroll
        for (int k = 0; k < 64; k++) {
            const float4* w4 = (const float4*)(Ws + k * 64 + c * 16);
            float xv = g[k];
            float4 w0 = w4[0], w1 = w4[1], w2 = w4[2], w3 = w4[3];
            acc[0]  += xv * w0.x; acc[1]  += xv * w0.y; acc[2]  += xv * w0.z; acc[3]  += xv * w0.w;
            acc[4]  += xv * w1.x; acc[5]  += xv * w1.y; acc[6]  += xv * w1.z; acc[7]  += xv * w1.w;
            acc[8]  += xv * w2.x; acc[9]  += xv * w2.y; acc[10] += xv * w2.z; acc[11] += xv * w2.w;
            acc[12] += xv * w3.x; acc[13] += xv * w3.y; acc[14] += xv * w3.z; acc[15] += xv * w3.w;
        }
#pragma unroll
        for (int q = 0; q < 4; q++) {
            float4 xo = xr[c * 4 + q];
            float4 o;
            o.x = sg * acc[q*4+0] + omg * xo.x;
            o.y = sg * acc[q*4+1] + omg * xo.y;
            o.z = sg * acc[q*4+2] + omg * xo.z;
            o.w = sg * acc[q*4+3] + omg * xo.w;
            xr[c * 4 + q] = o;
        }
    }
}

// ---------------- final pool + linear ----------------
__global__ void k_zero_out(float* out) { out[0] = 0.f; }

__global__ void k_final(const float* __restrict__ lw, const float* __restrict__ lb,
                        float* out) {
    float acc = 0.f;
    const int total = 2 * NN * 64;
    for (int i = blockIdx.x * blockDim.x + threadIdx.x; i < total;
         i += gridDim.x * blockDim.x) {
        float v = (i < NN * 64) ? gXA[i] : gXB[i - NN * 64];
        acc += v * lw[i & 63];
    }
    __shared__ float red[256];
    red[threadIdx.x] = acc;
    __syncthreads();
    for (int s = 128; s; s >>= 1) {
        if (threadIdx.x < s) red[threadIdx.x] += red[threadIdx.x + s];
        __syncthreads();
    }
    if (threadIdx.x == 0) {
        float v = red[0];
        if (blockIdx.x == 0) v += lb[0];
        atomicAdd(out, v);
    }
}

// ---------------- launch ----------------
extern "C" void kernel_launch(void* const* d_in, const int* in_sizes, int n_in,
                              void* d_out, int out_size) {
    const float* xA   = (const float*)d_in[0];
    const float* xB   = (const float*)d_in[1];
    const float* Wk   = (const float*)d_in[2];
    const float* bk   = (const float*)d_in[3];
    const float* Wq   = (const float*)d_in[4];
    const float* bq   = (const float*)d_in[5];
    const float* Wv   = (const float*)d_in[6];
    const float* bv   = (const float*)d_in[7];
    const float* Ar   = (const float*)d_in[8];
    const float* Mr   = (const float*)d_in[9];
    const float* pr   = (const float*)d_in[10];
    const float* Wa   = (const float*)d_in[11];
    const float* ba   = (const float*)d_in[12];
    const float* skip = (const float*)d_in[13];
    const float* lw   = (const float*)d_in[14];
    const float* lb   = (const float*)d_in[15];
    const int* e0 = (const int*)d_in[16];
    const int* e1 = (const int*)d_in[17];
    const int* e2 = (const int*)d_in[18];

    k_copyin<<<NN * 64 / 256, 256>>>(xA, xB);

    // batched CSR build, multi-block scan
    k_zero_deg<<<dim3(NN / 256, 3), 256>>>();
    k_hist<<<dim3((EE + 255) / 256, 3), 256>>>(e0, e1, e2);
    k_blocksum<<<dim3(128, 3), 1024>>>();
    k_scanblk<<<1, 128>>>();
    k_scanlocal<<<dim3(128, 3), 1024>>>();
    k_scatter<<<dim3((EE + 255) / 256, 3), 256>>>(e0, e1, e2);

    for (int l = 0; l < 3; l++) {
        k_fuse<<<130, 256>>>(Wk, bk, Wq, bq, Wv, bv, Ar, Mr, l);
        k_proj<<<dim3(512, 5), 256>>>(0);
        k_proj<<<dim3(512, 3), 256>>>(1);
        k_edge_B<<<16384, 256>>>(pr, l);
        k_edge_A<<<16384, 256>>>(pr, l);
        k_out<<<512, 256>>>(0, Wa, ba, skip, l);
        k_out<<<512, 256>>>(1, Wa, ba, skip, l);
    }

    k_zero_out<<<1, 1>>>((float*)d_out);
    k_final<<<1024, 256>>>(lw, lb, (float*)d_out);
}

// round 3
// speedup vs baseline: 1.3957x; 1.0647x over previous
#include <cuda_runtime.h>
#include <math.h>

#define NN 131072
#define EE 1000000

typedef unsigned long long u64;

// ---------------- static device scratch (no allocs allowed) ----------------
__device__ __align__(128) float gXA[NN * 64];
__device__ __align__(128) float gXB[NN * 64];
__device__ __align__(128) float gBufA[(size_t)NN * 320]; // [q | rel0 kv-interleaved | rel2 kv-interleaved]
__device__ __align__(128) float gBufB[(size_t)NN * 192]; // [q | rel1 kv-interleaved]
__device__ __align__(128) float gAggA[NN * 64];
__device__ __align__(128) float gAggB[NN * 64];
__device__ __align__(128) float gWfA[64 * 320];
__device__ float gBfA[320];
__device__ __align__(128) float gWfB[64 * 192];
__device__ float gBfB[192];
__device__ int   gRowptr[3][NN + 1];
__device__ int   gCur3[3][NN];
__device__ int   gBlkSum[3][128];
__device__ int   gCsr[3][EE];

// ---------------- packed f32x2 helpers (sm_103a FFMA2 path) ----------------
__device__ __forceinline__ u64 packf2(float x, float y) {
    u64 r; asm("mov.b64 %0, {%1, %2};" : "=l"(r) : "f"(x), "f"(y)); return r;
}
__device__ __forceinline__ void fma2(u64& d, u64 a, u64 b) {   // d += a*b (packed)
    asm("fma.rn.f32x2 %0, %1, %2, %0;" : "+l"(d) : "l"(a), "l"(b));
}
__device__ __forceinline__ u64 mul2(u64 a, u64 b) {
    u64 r; asm("mul.rn.f32x2 %0, %1, %2;" : "=l"(r) : "l"(a), "l"(b)); return r;
}

// ---------------- misc helpers ----------------
__device__ __forceinline__ float warpsum(float p) {
    p += __shfl_xor_sync(0xffffffffu, p, 16);
    p += __shfl_xor_sync(0xffffffffu, p, 8);
    p += __shfl_xor_sync(0xffffffffu, p, 4);
    p += __shfl_xor_sync(0xffffffffu, p, 2);
    p += __shfl_xor_sync(0xffffffffu, p, 1);
    return p;
}
__device__ __forceinline__ int wscan_incl(int x, int lane) {
#pragma unroll
    for (int o = 1; o < 32; o <<= 1) {
        int y = __shfl_up_sync(0xffffffffu, x, o);
        if (lane >= o) x += y;
    }
    return x;
}
__device__ __forceinline__ float gelu_f(float v) {
    return 0.5f * v * (1.0f + erff(v * 0.7071067811865476f));
}

// ---------------- input staging ----------------
__global__ void k_copyin(const float* __restrict__ xA, const float* __restrict__ xB) {
    int i = blockIdx.x * blockDim.x + threadIdx.x;
    gXA[i] = xA[i];
    gXB[i] = xB[i];
}

// ---------------- CSR build ----------------
__global__ void k_zero_deg() {
    int rel = blockIdx.y;
    int i = blockIdx.x * blockDim.x + threadIdx.x;
    if (i < NN) gRowptr[rel][i] = 0;
}

__global__ void k_hist(const int* __restrict__ e0, const int* __restrict__ e1,
                       const int* __restrict__ e2) {
    int rel = blockIdx.y;
    const int* ei = rel == 0 ? e0 : rel == 1 ? e1 : e2;
    int e = blockIdx.x * blockDim.x + threadIdx.x;
    if (e < EE) atomicAdd(&gRowptr[rel][ei[EE + e]], 1);
}

__global__ void k_blocksum() {
    int rel = blockIdx.y;
    int i = blockIdx.x * 1024 + threadIdx.x;
    int lane = threadIdx.x & 31, wid = threadIdx.x >> 5;
    int s = gRowptr[rel][i];
#pragma unroll
    for (int o = 16; o; o >>= 1) s += __shfl_xor_sync(0xffffffffu, s, o);
    __shared__ int sh[32];
    if (lane == 0) sh[wid] = s;
    __syncthreads();
    if (wid == 0) {
        int t = sh[lane];
#pragma unroll
        for (int o = 16; o; o >>= 1) t += __shfl_xor_sync(0xffffffffu, t, o);
        if (lane == 0) gBlkSum[rel][blockIdx.x] = t;
    }
}

__global__ void k_scanblk() {
    int tid = threadIdx.x, lane = tid & 31, wid = tid >> 5;
    __shared__ int ws[4];
    for (int rel = 0; rel < 3; rel++) {
        int v = gBlkSum[rel][tid];
        int x = wscan_incl(v, lane);
        __syncthreads();
        if (lane == 31) ws[wid] = x;
        __syncthreads();
        int add = 0;
#pragma unroll
        for (int w = 0; w < 4; w++) add += (w < wid) ? ws[w] : 0;
        gBlkSum[rel][tid] = x + add - v;
        __syncthreads();
    }
}

__global__ void k_scanlocal() {
    int rel = blockIdx.y;
    int idx = blockIdx.x * 1024 + threadIdx.x;
    int lane = threadIdx.x & 31, wid = threadIdx.x >> 5;
    int v = gRowptr[rel][idx];
    int x = wscan_incl(v, lane);
    __shared__ int ws[32];
    if (lane == 31) ws[wid] = x;
    __syncthreads();
    if (wid == 0) ws[lane] = wscan_incl(ws[lane], lane);
    __syncthreads();
    int incl = x + (wid ? ws[wid - 1] : 0);
    int excl = incl - v + gBlkSum[rel][blockIdx.x];
    gRowptr[rel][idx] = excl;
    gCur3[rel][idx] = excl;
    if (idx == NN - 1) gRowptr[rel][NN] = excl + v;
}

__global__ void k_scatter(const int* __restrict__ e0, const int* __restrict__ e1,
                          const int* __restrict__ e2) {
    int rel = blockIdx.y;
    const int* ei = rel == 0 ? e0 : rel == 1 ? e1 : e2;
    int e = blockIdx.x * blockDim.x + threadIdx.x;
    if (e >= EE) return;
    int dst = ei[EE + e];
    int pos = atomicAdd(&gCur3[rel][dst], 1);
    gCsr[rel][pos] = ei[e];
}

// ---------------- per-layer fused weight build (kv interleave perm) --------
__device__ float fuse_elem(int typ, int i, int j, int l,
                           const float* __restrict__ Wk, const float* __restrict__ bk,
                           const float* __restrict__ Wq, const float* __restrict__ bq,
                           const float* __restrict__ Wv, const float* __restrict__ bv,
                           const float* __restrict__ Ar, const float* __restrict__ Mr) {
    if (j < 64) {
        if (i >= 0) return Wq[(size_t)(l * 2 + typ) * 4096 + i * 64 + j];
        return bq[(l * 2 + typ) * 64 + j];
    }
    int t = j - 64, rel;
    if (typ == 0) { rel = (t >> 7) ? 2 : 0; t &= 127; }
    else rel = 1;
    int lane = t >> 2, c = t & 3;
    int isK = (c < 2);
    int dcol = 2 * lane + (c & 1);
    const float* R = (isK ? Ar : Mr) + (size_t)(l * 3 + rel) * 4096;
    float s = 0.f;
    if (i >= 0) {
        const float* w = (isK ? Wk : Wv) + (size_t)(l * 2 + typ) * 4096 + i * 64;
#pragma unroll
        for (int d = 0; d < 64; d++) s += w[d] * R[d * 64 + dcol];
    } else {
        const float* b = (isK ? bk : bv) + (l * 2 + typ) * 64;
#pragma unroll
        for (int d = 0; d < 64; d++) s += b[d] * R[d * 64 + dcol];
    }
    return s;
}

__global__ void k_fuse(const float* __restrict__ Wk, const float* __restrict__ bk,
                       const float* __restrict__ Wq, const float* __restrict__ bq,
                       const float* __restrict__ Wv, const float* __restrict__ bv,
                       const float* __restrict__ Ar, const float* __restrict__ Mr, int l) {
    int id = blockIdx.x * blockDim.x + threadIdx.x;
    if (id < 20480) {
        int i = id / 320, j = id % 320;
        gWfA[id] = fuse_elem(0, i, j, l, Wk, bk, Wq, bq, Wv, bv, Ar, Mr);
    } else if (id < 32768) {
        int idx = id - 20480;
        int i = idx / 192, j = idx % 192;
        gWfB[idx] = fuse_elem(1, i, j, l, Wk, bk, Wq, bq, Wv, bv, Ar, Mr);
    } else if (id < 33088) {
        int j = id - 32768;
        gBfA[j] = fuse_elem(0, -1, j, l, Wk, bk, Wq, bq, Wv, bv, Ar, Mr);
    } else if (id < 33280) {
        int j = id - 33088;
        gBfB[j] = fuse_elem(1, -1, j, l, Wk, bk, Wq, bq, Wv, bv, Ar, Mr);
    }
}

// ---------------- wide projection GEMM (packed f32x2): buf = x @ Wf + bf ---
__global__ void __launch_bounds__(256) k_proj(int typ) {
    const float* X   = typ ? gXB  : gXA;
    const float* Wf  = typ ? gWfB : gWfA;
    const float* Bf  = typ ? gBfB : gBfA;
    float*       Out = typ ? gBufB : gBufA;
    const int OC = typ ? 192 : 320;
    int cg = blockIdx.y;

    __shared__ __align__(16) float Ws[4096];
    __shared__ float Bs[64];
    for (int i = threadIdx.x; i < 4096; i += 256) {
        int k = i >> 6, j = i & 63;
        Ws[i] = Wf[k * OC + cg * 64 + j];
    }
    if (threadIdx.x < 64) Bs[threadIdx.x] = Bf[cg * 64 + threadIdx.x];
    __syncthreads();

    size_t r = (size_t)blockIdx.x * 256 + threadIdx.x;
    float x[64];
    const float4* xr = (const float4*)(X + r * 64);
#pragma unroll
    for (int i = 0; i < 16; i++) {
        float4 t = xr[i];
        x[4*i] = t.x; x[4*i+1] = t.y; x[4*i+2] = t.z; x[4*i+3] = t.w;
    }
    ulonglong2* outp = (ulonglong2*)(Out + r * OC + cg * 64);
#pragma unroll
    for (int c = 0; c < 4; c++) {
        u64 acc[8];
#pragma unroll
        for (int j = 0; j < 8; j++) acc[j] = packf2(Bs[c * 16 + 2*j], Bs[c * 16 + 2*j + 1]);
#pragma unroll
        for (int k = 0; k < 64; k++) {
            u64 xx = packf2(x[k], x[k]);
            const ulonglong2* w2 = (const ulonglong2*)(Ws + k * 64 + c * 16);
            ulonglong2 w01 = w2[0], w23 = w2[1], w45 = w2[2], w67 = w2[3];
            fma2(acc[0], w01.x, xx); fma2(acc[1], w01.y, xx);
            fma2(acc[2], w23.x, xx); fma2(acc[3], w23.y, xx);
            fma2(acc[4], w45.x, xx); fma2(acc[5], w45.y, xx);
            fma2(acc[6], w67.x, xx); fma2(acc[7], w67.y, xx);
        }
#pragma unroll
        for (int q = 0; q < 4; q++) {
            ulonglong2 s; s.x = acc[2*q]; s.y = acc[2*q + 1];
            outp[c * 4 + q] = s;
        }
    }
}

// ---------------- edge attention: one kernel per relation, online softmax --
template <int REL, int ACCUM>
__global__ void k_edge(const float* __restrict__ p_rel, int l) {
    int t = blockIdx.x * blockDim.x + threadIdx.x;
    int gw = t >> 5, lane = t & 31;
    if (gw >= NN) return;

    const float* Q;   int qs;
    const float* Src; int ss, off;
    float* Agg;
    if (REL == 0) { Q = gBufB; qs = 192; Src = gBufA; ss = 320; off = 64;  Agg = gAggB; }
    else if (REL == 1) { Q = gBufA; qs = 320; Src = gBufB; ss = 192; off = 64;  Agg = gAggA; }
    else { Q = gBufA; qs = 320; Src = gBufA; ss = 320; off = 192; Agg = gAggA; }

    float scl = p_rel[l * 3 + REL] * 0.125f;
    float2 q = *(const float2*)(Q + (size_t)gw * qs + 2 * lane);

    const int* __restrict__ rowptr = gRowptr[REL];
    const int* __restrict__ csr = gCsr[REL];
    int beg = rowptr[gw], end = rowptr[gw + 1];

    float mx = -3.0e38f, den = 0.f, s0 = 0.f, s1 = 0.f;
    for (int j = beg; j < end; j++) {
        int s = __ldg(&csr[j]);
        float4 kv = *(const float4*)(Src + (size_t)s * ss + off + 4 * lane);
        float sc = warpsum(fmaf(q.x, kv.x, q.y * kv.y)) * scl;
        if (sc > mx) {                      // warp-uniform branch
            float f = __expf(mx - sc);      // first iter: exp(-huge) = 0
            den = den * f + 1.f;
            s0  = s0 * f + kv.z;
            s1  = s1 * f + kv.w;
            mx = sc;
        } else {
            float ex = __expf(sc - mx);
            den += ex;
            s0  += ex * kv.z;
            s1  += ex * kv.w;
        }
    }
    float a0 = 0.f, a1 = 0.f;
    if (den > 0.f) {
        float inv = 1.0f / den;
        a0 = s0 * inv;
        a1 = s1 * inv;
    }
    float2* ap = (float2*)(Agg + (size_t)gw * 64 + 2 * lane);
    if (ACCUM) {
        float2 old = *ap;
        *ap = make_float2(old.x + a0, old.y + a1);
    } else {
        *ap = make_float2(a0, a1);
    }
}

// ---------------- output projection + skip (packed f32x2), in-place x ------
__global__ void __launch_bounds__(256) k_out(int typ, const float* __restrict__ Wa,
                                             const float* __restrict__ ba,
                                             const float* __restrict__ skip, int l) {
    __shared__ __align__(16) float Ws[4096];
    __shared__ float Bs[64];
    const float* agg = typ ? gAggB : gAggA;
    float* X = typ ? gXB : gXA;
    const float* w = Wa + (size_t)(l * 2 + typ) * 4096;
    for (int i = threadIdx.x; i < 4096; i += 256) Ws[i] = w[i];
    if (threadIdx.x < 64) Bs[threadIdx.x] = ba[(l * 2 + typ) * 64 + threadIdx.x];
    __syncthreads();

    float sg = 1.0f / (1.0f + __expf(-skip[l * 2 + typ]));
    float omg = 1.0f - sg;
    u64 sgp = packf2(sg, sg), omgp = packf2(omg, omg);
    size_t r = (size_t)blockIdx.x * 256 + threadIdx.x;

    float g[64];
    const float4* ar = (const float4*)(agg + r * 64);
#pragma unroll
    for (int i = 0; i < 16; i++) {
        float4 t = ar[i];
        g[4*i]   = gelu_f(t.x);
        g[4*i+1] = gelu_f(t.y);
        g[4*i+2] = gelu_f(t.z);
        g[4*i+3] = gelu_f(t.w);
    }
    ulonglong2* xr = (ulonglong2*)(X + r * 64);
#pragma unroll
    for (int c = 0; c < 4; c++) {
        u64 acc[8];
#pragma unroll
        for (int j = 0; j < 8; j++) acc[j] = packf2(Bs[c * 16 + 2*j], Bs[c * 16 + 2*j + 1]);
#pragma unroll
        for (int k = 0; k < 64; k++) {
            u64 xx = packf2(g[k], g[k]);
            const ulonglong2* w2 = (const ulonglong2*)(Ws + k * 64 + c * 16);
            ulonglong2 w01 = w2[0], w23 = w2[1], w45 = w2[2], w67 = w2[3];
            fma2(acc[0], w01.x, xx); fma2(acc[1], w01.y, xx);
            fma2(acc[2], w23.x, xx); fma2(acc[3], w23.y, xx);
            fma2(acc[4], w45.x, xx); fma2(acc[5], w45.y, xx);
            fma2(acc[6], w67.x, xx); fma2(acc[7], w67.y, xx);
        }
#pragma unroll
        for (int q = 0; q < 4; q++) {
            ulonglong2 xo = xr[c * 4 + q];
            u64 y0 = mul2(xo.x, omgp); fma2(y0, acc[2*q],     sgp);
            u64 y1 = mul2(xo.y, omgp); fma2(y1, acc[2*q + 1], sgp);
            ulonglong2 s; s.x = y0; s.y = y1;
            xr[c * 4 + q] = s;
        }
    }
}

// ---------------- final pool + linear ----------------
__global__ void k_zero_out(float* out) { out[0] = 0.f; }

__global__ void k_final(const float* __restrict__ lw, const float* __restrict__ lb,
                        float* out) {
    float acc = 0.f;
    const int total = 2 * NN * 64;
    for (int i = blockIdx.x * blockDim.x + threadIdx.x; i < total;
         i += gridDim.x * blockDim.x) {
        float v = (i < NN * 64) ? gXA[i] : gXB[i - NN * 64];
        acc += v * lw[i & 63];
    }
    __shared__ float red[256];
    red[threadIdx.x] = acc;
    __syncthreads();
    for (int s = 128; s; s >>= 1) {
        if (threadIdx.x < s) red[threadIdx.x] += red[threadIdx.x + s];
        __syncthreads();
    }
    if (threadIdx.x == 0) {
        float v = red[0];
        if (blockIdx.x == 0) v += lb[0];
        atomicAdd(out, v);
    }
}

// ---------------- launch ----------------
extern "C" void kernel_launch(void* const* d_in, const int* in_sizes, int n_in,
                              void* d_out, int out_size) {
    const float* xA   = (const float*)d_in[0];
    const float* xB   = (const float*)d_in[1];
    const float* Wk   = (const float*)d_in[2];
    const float* bk   = (const float*)d_in[3];
    const float* Wq   = (const float*)d_in[4];
    const float* bq   = (const float*)d_in[5];
    const float* Wv   = (const float*)d_in[6];
    const float* bv   = (const float*)d_in[7];
    const float* Ar   = (const float*)d_in[8];
    const float* Mr   = (const float*)d_in[9];
    const float* pr   = (const float*)d_in[10];
    const float* Wa   = (const float*)d_in[11];
    const float* ba   = (const float*)d_in[12];
    const float* skip = (const float*)d_in[13];
    const float* lw   = (const float*)d_in[14];
    const float* lb   = (const float*)d_in[15];
    const int* e0 = (const int*)d_in[16];
    const int* e1 = (const int*)d_in[17];
    const int* e2 = (const int*)d_in[18];

    k_copyin<<<NN * 64 / 256, 256>>>(xA, xB);

    k_zero_deg<<<dim3(NN / 256, 3), 256>>>();
    k_hist<<<dim3((EE + 255) / 256, 3), 256>>>(e0, e1, e2);
    k_blocksum<<<dim3(128, 3), 1024>>>();
    k_scanblk<<<1, 128>>>();
    k_scanlocal<<<dim3(128, 3), 1024>>>();
    k_scatter<<<dim3((EE + 255) / 256, 3), 256>>>(e0, e1, e2);

    for (int l = 0; l < 3; l++) {
        k_fuse<<<130, 256>>>(Wk, bk, Wq, bq, Wv, bv, Ar, Mr, l);
        k_proj<<<dim3(512, 5), 256>>>(0);
        k_proj<<<dim3(512, 3), 256>>>(1);
        // one relation per kernel: each gather working set (64MB) fits L2
        k_edge<0, 0><<<16384, 256>>>(pr, l);   // A -> B, writes gAggB
        k_edge<1, 0><<<16384, 256>>>(pr, l);   // B -> A, writes gAggA
        k_edge<2, 1><<<16384, 256>>>(pr, l);   // A -> A, accumulates gAggA
        k_out<<<512, 256>>>(0, Wa, ba, skip, l);
        k_out<<<512, 256>>>(1, Wa, ba, skip, l);
    }

    k_zero_out<<<1, 1>>>((float*)d_out);
    k_final<<<1024, 256>>>(lw, lb, (float*)d_out);
}